// round 1
// baseline (speedup 1.0000x reference)
#include <cuda_runtime.h>

#define N_NODES 160000
#define NODES_PER_GRAPH 20000
#define NBATCH 8
#define N_EDGES 5120000
#define HID 16

// ---------------- device scratch (no allocation allowed) ----------------
__device__ float d_s1[N_NODES];            // layer-1 scalar aggregation
__device__ float d_p[N_NODES];             // h . Wr2 per node
__device__ float d_gt[N_NODES];            // h2 transposed: [20000][8]
__device__ float d_y1[4000 * NBATCH];      // layer outputs, transposed [J][8]
__device__ float d_y2[800 * NBATCH];
__device__ float d_y3[160 * NBATCH];

// ---------------- kernels ----------------

__global__ void zero_s1() {
    int i = blockIdx.x * blockDim.x + threadIdx.x;
    if (i < N_NODES) d_s1[i] = 0.f;
}

// pass 1: s1[tgt] += ew * x[src]
__global__ void edge_pass1(const int* __restrict__ src, const int* __restrict__ tgt,
                           const float* __restrict__ ew, const float* __restrict__ x) {
    int i = blockIdx.x * blockDim.x + threadIdx.x;
    int base = i * 4;
    if (base >= N_EDGES) return;
    int4   s = *(const int4*)(src + base);
    int4   t = *(const int4*)(tgt + base);
    float4 w = *(const float4*)(ew + base);
    atomicAdd(&d_s1[t.x], w.x * __ldg(&x[s.x]));
    atomicAdd(&d_s1[t.y], w.y * __ldg(&x[s.y]));
    atomicAdd(&d_s1[t.z], w.z * __ldg(&x[s.z]));
    atomicAdd(&d_s1[t.w], w.w * __ldg(&x[s.w]));
}

// per node: compute p[n] (for pass 2) and initialize gt with q[n] + br2
__global__ void node_kernel(const float* __restrict__ x,
                            const float* __restrict__ Wr1, const float* __restrict__ br1,
                            const float* __restrict__ Ws1, const float* __restrict__ Wr2,
                            const float* __restrict__ br2, const float* __restrict__ Ws2) {
    int n = blockIdx.x * blockDim.x + threadIdx.x;
    if (n >= N_NODES) return;
    float s  = d_s1[n];
    float xv = x[n];
    float pa = 0.f, qa = 0.f;
#pragma unroll
    for (int f = 0; f < HID; f++) {
        float h = fmaf(s, __ldg(&Wr1[f]), fmaf(xv, __ldg(&Ws1[f]), __ldg(&br1[f])));
        h = fmaxf(h, 0.f);
        pa = fmaf(__ldg(&Wr2[f]), h, pa);
        qa = fmaf(__ldg(&Ws2[f]), h, qa);
    }
    d_p[n] = pa;
    unsigned nu = (unsigned)n;
    unsigned b  = nu / NODES_PER_GRAPH;
    unsigned k  = nu - b * NODES_PER_GRAPH;
    d_gt[k * NBATCH + b] = qa + __ldg(&br2[0]);
}

// pass 2: gt[transposed(tgt)] += ew * p[src]
__global__ void edge_pass2(const int* __restrict__ src, const int* __restrict__ tgt,
                           const float* __restrict__ ew) {
    int i = blockIdx.x * blockDim.x + threadIdx.x;
    int base = i * 4;
    if (base >= N_EDGES) return;
    int4   s = *(const int4*)(src + base);
    int4   t = *(const int4*)(tgt + base);
    float4 w = *(const float4*)(ew + base);
#define EP2_ONE(SS, TT, WW)                                            \
    {                                                                  \
        unsigned tu = (unsigned)(TT);                                  \
        unsigned b  = tu / NODES_PER_GRAPH;                            \
        unsigned k  = tu - b * NODES_PER_GRAPH;                        \
        atomicAdd(&d_gt[k * NBATCH + b], (WW) * __ldg(&d_p[SS]));      \
    }
    EP2_ONE(s.x, t.x, w.x);
    EP2_ONE(s.y, t.y, w.y);
    EP2_ONE(s.z, t.z, w.z);
    EP2_ONE(s.w, t.w, w.w);
#undef EP2_ONE
}

// batch-8 GEMV: out_t[j][b] = relu?( bias[j] + sum_k W[j,k] * in_t[k][b] )
// in/out selected from device globals (avoids host-side symbol address).
__global__ void gemm8(const float* __restrict__ W, const float* __restrict__ bias,
                      int which_in, int which_out, int K, int do_relu) {
    const float* __restrict__ gin =
        (which_in == 0) ? d_gt : (which_in == 1) ? d_y1 : d_y2;
    float* __restrict__ gout =
        (which_out == 0) ? d_y1 : (which_out == 1) ? d_y2 : d_y3;

    __shared__ float red[64][8];
    int j0 = blockIdx.x * 8;

    float acc[8][8];
#pragma unroll
    for (int j = 0; j < 8; j++)
#pragma unroll
        for (int b = 0; b < 8; b++) acc[j][b] = 0.f;

    for (int k = threadIdx.x; k < K; k += 256) {
        float4 ga = __ldg((const float4*)(gin + (size_t)k * 8));
        float4 gb = __ldg((const float4*)(gin + (size_t)k * 8 + 4));
        float g[8] = {ga.x, ga.y, ga.z, ga.w, gb.x, gb.y, gb.z, gb.w};
#pragma unroll
        for (int j = 0; j < 8; j++) {
            float w = __ldg(&W[(size_t)(j0 + j) * K + k]);
#pragma unroll
            for (int b = 0; b < 8; b++) acc[j][b] = fmaf(w, g[b], acc[j][b]);
        }
    }

    int lane = threadIdx.x & 31;
    int wid  = threadIdx.x >> 5;
#pragma unroll
    for (int j = 0; j < 8; j++) {
#pragma unroll
        for (int b = 0; b < 8; b++) {
            float v = acc[j][b];
#pragma unroll
            for (int o = 16; o > 0; o >>= 1)
                v += __shfl_down_sync(0xffffffffu, v, o);
            if (lane == 0) red[j * 8 + b][wid] = v;
        }
    }
    __syncthreads();
    if (threadIdx.x < 64) {
        int j = threadIdx.x >> 3;
        int b = threadIdx.x & 7;
        float v = 0.f;
#pragma unroll
        for (int w = 0; w < 8; w++) v += red[threadIdx.x][w];
        v += __ldg(&bias[j0 + j]);
        if (do_relu) v = fmaxf(v, 0.f);
        gout[(j0 + j) * 8 + b] = v;
    }
}

// final layer [8,160] @ W4^T [160,10] + b4, then log_softmax per row.
// 8 warps, one per graph; lanes 0..9 each own one class.
__global__ void final_kernel(const float* __restrict__ W4, const float* __restrict__ b4,
                             float* __restrict__ out) {
    int b    = threadIdx.x >> 5;   // batch (warp id)
    int lane = threadIdx.x & 31;
    float z = -1e30f;
    if (lane < 10) {
        float acc = __ldg(&b4[lane]);
#pragma unroll 8
        for (int k = 0; k < 160; k++)
            acc = fmaf(__ldg(&W4[lane * 160 + k]), d_y3[k * 8 + b], acc);
        z = acc;
    }
    float m = z;
#pragma unroll
    for (int o = 16; o > 0; o >>= 1)
        m = fmaxf(m, __shfl_xor_sync(0xffffffffu, m, o));
    float e = (lane < 10) ? __expf(z - m) : 0.f;
    float ssum = e;
#pragma unroll
    for (int o = 16; o > 0; o >>= 1)
        ssum += __shfl_xor_sync(0xffffffffu, ssum, o);
    if (lane < 10) out[b * 10 + lane] = z - m - __logf(ssum);
}

// ---------------- launch ----------------
extern "C" void kernel_launch(void* const* d_in, const int* in_sizes, int n_in,
                              void* d_out, int out_size) {
    const float* x   = (const float*)d_in[0];
    const float* ew  = (const float*)d_in[1];
    const float* Wr1 = (const float*)d_in[2];
    const float* br1 = (const float*)d_in[3];
    const float* Ws1 = (const float*)d_in[4];
    const float* Wr2 = (const float*)d_in[5];
    const float* br2 = (const float*)d_in[6];
    const float* Ws2 = (const float*)d_in[7];
    const float* W1  = (const float*)d_in[8];
    const float* b1  = (const float*)d_in[9];
    const float* W2  = (const float*)d_in[10];
    const float* b2  = (const float*)d_in[11];
    const float* W3  = (const float*)d_in[12];
    const float* b3  = (const float*)d_in[13];
    const float* W4  = (const float*)d_in[14];
    const float* b4  = (const float*)d_in[15];
    const int*   ei  = (const int*)d_in[16];
    const int* src = ei;
    const int* tgt = ei + N_EDGES;
    float* out = (float*)d_out;

    zero_s1<<<(N_NODES + 255) / 256, 256>>>();
    edge_pass1<<<(N_EDGES / 4 + 255) / 256, 256>>>(src, tgt, ew, x);
    node_kernel<<<(N_NODES + 255) / 256, 256>>>(x, Wr1, br1, Ws1, Wr2, br2, Ws2);
    edge_pass2<<<(N_EDGES / 4 + 255) / 256, 256>>>(src, tgt, ew);
    gemm8<<<500, 256>>>(W1, b1, 0, 0, 20000, 1);   // 20000 -> 4000
    gemm8<<<100, 256>>>(W2, b2, 1, 1, 4000, 1);    // 4000 -> 800
    gemm8<<<20, 256>>>(W3, b3, 2, 2, 800, 1);      // 800 -> 160
    final_kernel<<<1, 256>>>(W4, b4, out);         // 160 -> 10 + log_softmax
}